// round 3
// baseline (speedup 1.0000x reference)
#include <cuda_runtime.h>
#include <cstdint>

#define NROWS 10000
#define NFEAT 3000
#define NHID  32
#define KCLUS 10

// Scratch (allocation-free: __device__ globals)
__device__ __align__(16) float g_support[NROWS * NHID];
__device__ __align__(16) float g_z[NROWS * NHID];

// ---------------------------------------------------------------------------
// Zero the split-K accumulation buffers (graph replays re-accumulate!)
// ---------------------------------------------------------------------------
__global__ void zero_scratch() {
    int i = blockIdx.x * blockDim.x + threadIdx.x;
    if (i < (NROWS * NHID) / 4) {
        ((float4*)g_support)[i] = make_float4(0.f, 0.f, 0.f, 0.f);
        ((float4*)g_z)[i]       = make_float4(0.f, 0.f, 0.f, 0.f);
    }
}

// ---------------------------------------------------------------------------
// Thin GEMM: C[M,32] += A[M,K] @ B[K,32], split-K via blockIdx.y + atomicAdd.
// BM=128, BK=32, 256 threads, per-thread 4 rows x 4 cols with f32x2 packed FMA.
// klen MUST be a multiple of BK so float4 global loads stay 16B-aligned.
// ---------------------------------------------------------------------------
__global__ __launch_bounds__(256, 2)
void gemm_thin(const float* __restrict__ A, const float* __restrict__ B,
               float* __restrict__ C, int M, int K, int klen) {
    const int BM = 128, BK = 32;
    __shared__ __align__(16) float As[BM][BK + 1];  // +1 pad: conflict-free
    __shared__ __align__(16) float Bs[BK][NHID];    // rows 128B -> ulonglong2

    const int row0 = blockIdx.x * BM;
    const int kbeg = blockIdx.y * klen;             // multiple of 32
    const int kend = min(kbeg + klen, K);
    if (kbeg >= K) return;

    const int tid = threadIdx.x;
    const int tx  = tid & 7;    // col group (4 cols)
    const int ty  = tid >> 3;   // row group (4 rows), 0..31

    unsigned long long acc[4][2];
#pragma unroll
    for (int i = 0; i < 4; i++) { acc[i][0] = 0ull; acc[i][1] = 0ull; }

    const int lc4 = tid & 7;    // float4 index along k (loads)
    const int lr  = tid >> 3;   // 0..31

    for (int k0 = kbeg; k0 < kend; k0 += BK) {
        // ---- load A tile (128 x 32), zero-filled at edges ----
#pragma unroll
        for (int p = 0; p < 4; p++) {
            int rr   = lr + p * 32;
            int grow = row0 + rr;
            int gk   = k0 + lc4 * 4;                // 16B-aligned (k0 % 32 == 0)
            float4 v = make_float4(0.f, 0.f, 0.f, 0.f);
            if (grow < M) {
                if (gk + 4 <= kend) {
                    v = *(const float4*)(A + (size_t)grow * K + gk);
                } else {
                    float t0 = 0.f, t1 = 0.f, t2 = 0.f, t3 = 0.f;
                    if (gk + 0 < kend) t0 = A[(size_t)grow * K + gk + 0];
                    if (gk + 1 < kend) t1 = A[(size_t)grow * K + gk + 1];
                    if (gk + 2 < kend) t2 = A[(size_t)grow * K + gk + 2];
                    if (gk + 3 < kend) t3 = A[(size_t)grow * K + gk + 3];
                    v = make_float4(t0, t1, t2, t3);
                }
            }
            As[rr][lc4 * 4 + 0] = v.x;
            As[rr][lc4 * 4 + 1] = v.y;
            As[rr][lc4 * 4 + 2] = v.z;
            As[rr][lc4 * 4 + 3] = v.w;
        }
        // ---- load B tile (32 x 32) ----
        {
            int kk = lr;
            int gk = k0 + kk;
            float4 v = make_float4(0.f, 0.f, 0.f, 0.f);
            if (gk < kend) v = *(const float4*)(B + (size_t)gk * NHID + lc4 * 4);
            *(float4*)&Bs[kk][lc4 * 4] = v;
        }
        __syncthreads();

        // ---- compute: 16 MACs/thread/k via 8 packed fma.rn.f32x2 ----
#pragma unroll
        for (int k = 0; k < BK; k++) {
            ulonglong2 s = *(const ulonglong2*)&Bs[k][tx * 4];
#pragma unroll
            for (int i = 0; i < 4; i++) {
                unsigned int au = __float_as_uint(As[ty * 4 + i][k]);
                unsigned long long aa;
                asm("mov.b64 %0, {%1, %1};" : "=l"(aa) : "r"(au));
                asm("fma.rn.f32x2 %0, %1, %2, %0;" : "+l"(acc[i][0]) : "l"(aa), "l"(s.x));
                asm("fma.rn.f32x2 %0, %1, %2, %0;" : "+l"(acc[i][1]) : "l"(aa), "l"(s.y));
            }
        }
        __syncthreads();
    }

    // ---- epilogue: accumulate partial sums across K-splits ----
#pragma unroll
    for (int i = 0; i < 4; i++) {
        int row = row0 + ty * 4 + i;
        if (row < M) {
#pragma unroll
            for (int jp = 0; jp < 2; jp++) {
                unsigned int lo = (unsigned int)(acc[i][jp] & 0xffffffffull);
                unsigned int hi = (unsigned int)(acc[i][jp] >> 32);
                atomicAdd(&C[row * NHID + tx * 4 + jp * 2 + 0], __uint_as_float(lo));
                atomicAdd(&C[row * NHID + tx * 4 + jp * 2 + 1], __uint_as_float(hi));
            }
        }
    }
}

// ---------------------------------------------------------------------------
// Finalize: z = g_z + b (write), then student-t soft assignment q (write).
// One warp per row; lane = hidden index.
// ---------------------------------------------------------------------------
__global__ __launch_bounds__(256)
void finalize_kernel(const float* __restrict__ b, const float* __restrict__ mu,
                     float* __restrict__ out) {
    int warp = (blockIdx.x * blockDim.x + threadIdx.x) >> 5;
    int h    = threadIdx.x & 31;
    if (warp >= NROWS) return;

    float z = g_z[warp * NHID + h] + b[h];
    out[warp * NHID + h] = z;

    float d2[KCLUS];
#pragma unroll
    for (int j = 0; j < KCLUS; j++) {
        float diff = z - mu[j * NHID + h];
        float v = diff * diff;
#pragma unroll
        for (int off = 16; off; off >>= 1)
            v += __shfl_xor_sync(0xffffffffu, v, off);
        d2[j] = v;
    }

    float qv[KCLUS];
    float ssum = 0.f;
#pragma unroll
    for (int j = 0; j < KCLUS; j++) {
        float base = 1.0f / (1.0f + d2[j] * 5.0f + 1e-8f);  // ALPHA = 0.2
        qv[j] = 0.5f * powf(base, 1.2f);                    // ^(ALPHA+1) / 2
        ssum += qv[j];
    }
    if (h < KCLUS)
        out[NROWS * NHID + warp * KCLUS + h] = qv[h] / ssum;
}

// ---------------------------------------------------------------------------
extern "C" void kernel_launch(void* const* d_in, const int* in_sizes, int n_in,
                              void* d_out, int out_size) {
    const float* x   = (const float*)d_in[0];  // [10000, 3000]
    const float* adj = (const float*)d_in[1];  // [10000, 10000]
    const float* W   = (const float*)d_in[2];  // [3000, 32]
    const float* b   = (const float*)d_in[3];  // [32]
    const float* mu  = (const float*)d_in[4];  // [10, 32]
    float* out = (float*)d_out;                // z [10000,32] then q [10000,10]

    float *sup, *zbuf;
    cudaGetSymbolAddress((void**)&sup,  g_support);
    cudaGetSymbolAddress((void**)&zbuf, g_z);

    // 1. zero split-K accumulators
    zero_scratch<<<(NROWS * NHID / 4 + 255) / 256, 256>>>();

    // 2. support = x @ W   (79 row-blocks x 4 K-splits = 316 blocks)
    {
        dim3 grid((NROWS + 127) / 128, 4);
        int klen = ((NFEAT + 4 * 32 - 1) / (4 * 32)) * 32;  // 768 (multiple of BK)
        gemm_thin<<<grid, 256>>>(x, W, sup, NROWS, NFEAT, klen);
    }

    // 3. z = adj @ support  (316 blocks -> ~2 blocks/SM)
    {
        dim3 grid((NROWS + 127) / 128, 4);
        int klen = ((NROWS + 4 * 32 - 1) / (4 * 32)) * 32;  // 2528 (multiple of BK)
        gemm_thin<<<grid, 256>>>(adj, sup, zbuf, NROWS, NROWS, klen);
    }

    // 4. bias + soft assignment
    finalize_kernel<<<(NROWS * 32 + 255) / 256, 256>>>(b, mu, out);
}

// round 6
// speedup vs baseline: 3.0068x; 3.0068x over previous
#include <cuda_runtime.h>
#include <cuda_bf16.h>
#include <cstdint>

#define NROWS 10000
#define NFEAT 3000
#define NHID  32
#define KCLUS 10

__device__ __align__(16) float g_support[NROWS * NHID];
__device__ __align__(16) float g_z[NROWS * NHID];

#define AS_STRIDE 72   // bf16 elems per A smem row (144 B) -> conflict-free frags
#define BS_STRIDE 68   // bf16 elems per B smem row (136 B) -> worst 2-way

// ---------------------------------------------------------------------------
__global__ void zero_scratch() {
    int i = blockIdx.x * blockDim.x + threadIdx.x;
    if (i < (NROWS * NHID) / 4) {
        ((float4*)g_support)[i] = make_float4(0.f, 0.f, 0.f, 0.f);
        ((float4*)g_z)[i]       = make_float4(0.f, 0.f, 0.f, 0.f);
    }
}

// fp32 pair -> bf16 hi pair + bf16 lo (residual) pair, packed as u32
__device__ __forceinline__ void split2(float x, float y, uint32_t& h, uint32_t& l) {
    __nv_bfloat162 hb = __floats2bfloat162_rn(x, y);      // low = x, high = y
    float2 hf = __bfloat1622float2(hb);
    __nv_bfloat162 lb = __floats2bfloat162_rn(x - hf.x, y - hf.y);
    h = *reinterpret_cast<uint32_t*>(&hb);
    l = *reinterpret_cast<uint32_t*>(&lb);
}

#define MMA_BF16(dd, a, b0, b1)                                              \
    asm volatile(                                                            \
        "mma.sync.aligned.m16n8k16.row.col.f32.bf16.bf16.f32 "               \
        "{%0,%1,%2,%3}, {%4,%5,%6,%7}, {%8,%9}, {%0,%1,%2,%3};"              \
        : "+f"(dd[0]), "+f"(dd[1]), "+f"(dd[2]), "+f"(dd[3])                 \
        : "r"(a[0]), "r"(a[1]), "r"(a[2]), "r"(a[3]), "r"(b0), "r"(b1))

// ---------------------------------------------------------------------------
// C[M,32] += A[M,K] @ B[K,32] via mma.sync bf16 2-term split (hh + hl + lh).
// BM=128 (blockIdx.x), split-K (blockIdx.y), BK=64, single smem buffer with
// register prefetch of the next chunk overlapping the MMA block.
// ---------------------------------------------------------------------------
__global__ __launch_bounds__(256, 2)
void gemm_mma(const float* __restrict__ A, const float* __restrict__ B,
              float* __restrict__ C, int M, int K, int klen) {
    __shared__ __nv_bfloat16 Ah[128 * AS_STRIDE];
    __shared__ __nv_bfloat16 Al[128 * AS_STRIDE];
    __shared__ __nv_bfloat16 Bh[32 * BS_STRIDE];
    __shared__ __nv_bfloat16 Bl[32 * BS_STRIDE];

    const int tid  = threadIdx.x;
    const int warp = tid >> 5, lane = tid & 31;
    const int g    = lane >> 2, tg = lane & 3;   // mma group / thread-in-group
    const int wm   = warp * 16;                  // warp's row offset in tile
    const int row0 = blockIdx.x * 128;
    const int kbeg = blockIdx.y * klen;          // multiple of 64
    const int kend = min(kbeg + klen, K);
    const int nch  = (kend > kbeg) ? ((kend - kbeg + 63) >> 6) : 0;

    float d[4][4];
#pragma unroll
    for (int i = 0; i < 4; i++)
#pragma unroll
        for (int j = 0; j < 4; j++) d[i][j] = 0.f;

    float4 va[8];
    float  vb[8];

    // ---- global load of one chunk into registers ----
#define LOAD_CHUNK(k0)                                                        \
    {                                                                         \
        _Pragma("unroll")                                                     \
        for (int i = 0; i < 8; i++) {                                         \
            int f = tid + i * 256;                                            \
            int r = f >> 4, kc4 = f & 15;                                     \
            int grow = row0 + r, gk = (k0) + kc4 * 4;                         \
            va[i] = (grow < M && gk + 4 <= kend)                              \
                        ? *(const float4*)(A + (size_t)grow * K + gk)         \
                        : make_float4(0.f, 0.f, 0.f, 0.f);                    \
        }                                                                     \
        _Pragma("unroll")                                                     \
        for (int i = 0; i < 2; i++) {                                         \
            int f = tid + i * 256;                                            \
            int n = f & 31, kq = f >> 5;                                      \
            _Pragma("unroll")                                                 \
            for (int j = 0; j < 4; j++) {                                     \
                int kk = (k0) + kq * 4 + j;                                   \
                vb[i * 4 + j] = (kk < kend) ? B[(size_t)kk * NHID + n] : 0.f; \
            }                                                                 \
        }                                                                     \
    }

    if (nch > 0) LOAD_CHUNK(kbeg);

    for (int c = 0; c < nch; c++) {
        __syncthreads();   // previous compute done reading smem

        // ---- convert + store to smem ----
#pragma unroll
        for (int i = 0; i < 8; i++) {
            int f = tid + i * 256;
            int r = f >> 4, kc4 = f & 15;
            uint32_t h0, l0, h1, l1;
            split2(va[i].x, va[i].y, h0, l0);
            split2(va[i].z, va[i].w, h1, l1);
            int e = r * AS_STRIDE + kc4 * 4;
            *(uint2*)&Ah[e] = make_uint2(h0, h1);
            *(uint2*)&Al[e] = make_uint2(l0, l1);
        }
#pragma unroll
        for (int i = 0; i < 2; i++) {
            int f = tid + i * 256;
            int n = f & 31, kq = f >> 5;
            uint32_t h0, l0, h1, l1;
            split2(vb[i * 4 + 0], vb[i * 4 + 1], h0, l0);
            split2(vb[i * 4 + 2], vb[i * 4 + 3], h1, l1);
            int e = n * BS_STRIDE + kq * 4;
            *(uint2*)&Bh[e] = make_uint2(h0, h1);
            *(uint2*)&Bl[e] = make_uint2(l0, l1);
        }
        __syncthreads();

        // ---- prefetch next chunk (LDG latency hides behind MMAs) ----
        if (c + 1 < nch) LOAD_CHUNK(kbeg + (c + 1) * 64);

        // ---- compute: 4 k16-steps x 4 n-tiles x 3 products ----
#pragma unroll
        for (int ks = 0; ks < 4; ks++) {
            const int k0 = ks * 16;
            uint32_t ah[4], al[4];
            {
                int base = (wm + g) * AS_STRIDE + k0 + tg * 2;
                ah[0] = *(uint32_t*)&Ah[base];
                ah[1] = *(uint32_t*)&Ah[base + 8 * AS_STRIDE];
                ah[2] = *(uint32_t*)&Ah[base + 8];
                ah[3] = *(uint32_t*)&Ah[base + 8 * AS_STRIDE + 8];
                al[0] = *(uint32_t*)&Al[base];
                al[1] = *(uint32_t*)&Al[base + 8 * AS_STRIDE];
                al[2] = *(uint32_t*)&Al[base + 8];
                al[3] = *(uint32_t*)&Al[base + 8 * AS_STRIDE + 8];
            }
#pragma unroll
            for (int nt = 0; nt < 4; nt++) {
                int bbase = (nt * 8 + g) * BS_STRIDE + k0 + tg * 2;
                uint32_t bh0 = *(uint32_t*)&Bh[bbase];
                uint32_t bh1 = *(uint32_t*)&Bh[bbase + 8];
                uint32_t bl0 = *(uint32_t*)&Bl[bbase];
                uint32_t bl1 = *(uint32_t*)&Bl[bbase + 8];
                MMA_BF16(d[nt], ah, bh0, bh1);   // hi * hi
                MMA_BF16(d[nt], ah, bl0, bl1);   // hi * lo
                MMA_BF16(d[nt], al, bh0, bh1);   // lo * hi
            }
        }
    }

    // ---- epilogue: split-K accumulate into C ----
    const int r0 = row0 + wm + g;
#pragma unroll
    for (int nt = 0; nt < 4; nt++) {
        int c0 = nt * 8 + tg * 2;
        if (r0 < M) {
            atomicAdd(&C[r0 * NHID + c0],     d[nt][0]);
            atomicAdd(&C[r0 * NHID + c0 + 1], d[nt][1]);
        }
        if (r0 + 8 < M) {
            atomicAdd(&C[(r0 + 8) * NHID + c0],     d[nt][2]);
            atomicAdd(&C[(r0 + 8) * NHID + c0 + 1], d[nt][3]);
        }
    }
#undef LOAD_CHUNK
}

// ---------------------------------------------------------------------------
__global__ __launch_bounds__(256)
void finalize_kernel(const float* __restrict__ b, const float* __restrict__ mu,
                     float* __restrict__ out) {
    int warp = (blockIdx.x * blockDim.x + threadIdx.x) >> 5;
    int h    = threadIdx.x & 31;
    if (warp >= NROWS) return;

    float z = g_z[warp * NHID + h] + b[h];
    out[warp * NHID + h] = z;

    float d2[KCLUS];
#pragma unroll
    for (int j = 0; j < KCLUS; j++) {
        float diff = z - mu[j * NHID + h];
        float v = diff * diff;
#pragma unroll
        for (int off = 16; off; off >>= 1)
            v += __shfl_xor_sync(0xffffffffu, v, off);
        d2[j] = v;
    }

    float qv[KCLUS];
    float ssum = 0.f;
#pragma unroll
    for (int j = 0; j < KCLUS; j++) {
        float base = 1.0f / (1.0f + d2[j] * 5.0f + 1e-8f);  // ALPHA = 0.2
        qv[j] = 0.5f * __powf(base, 1.2f);                  // ^(ALPHA+1) / 2
        ssum += qv[j];
    }
    if (h < KCLUS)
        out[NROWS * NHID + warp * KCLUS + h] = qv[h] / ssum;
}

// ---------------------------------------------------------------------------
extern "C" void kernel_launch(void* const* d_in, const int* in_sizes, int n_in,
                              void* d_out, int out_size) {
    const float* x   = (const float*)d_in[0];  // [10000, 3000]
    const float* adj = (const float*)d_in[1];  // [10000, 10000]
    const float* W   = (const float*)d_in[2];  // [3000, 32]
    const float* b   = (const float*)d_in[3];  // [32]
    const float* mu  = (const float*)d_in[4];  // [10, 32]
    float* out = (float*)d_out;                // z [10000,32] then q [10000,10]

    float *sup, *zbuf;
    cudaGetSymbolAddress((void**)&sup,  g_support);
    cudaGetSymbolAddress((void**)&zbuf, g_z);

    zero_scratch<<<(NROWS * NHID / 4 + 255) / 256, 256>>>();

    // support = x @ W : 79 row tiles x 2 K-splits (klen multiple of 64)
    {
        dim3 grid(79, 2);
        gemm_mma<<<grid, 256>>>(x, W, sup, NROWS, NFEAT, 1536);
    }
    // z = adj @ support : 79 row tiles x 4 K-splits
    {
        dim3 grid(79, 4);
        gemm_mma<<<grid, 256>>>(adj, sup, zbuf, NROWS, NROWS, 2560);
    }

    finalize_kernel<<<(NROWS * 32 + 255) / 256, 256>>>(b, mu, out);
}

// round 8
// speedup vs baseline: 3.2337x; 1.0755x over previous
#include <cuda_runtime.h>
#include <cuda_bf16.h>
#include <cstdint>

#define NROWS 10000
#define NFEAT 3000
#define NHID  32
#define KCLUS 10

#define BSTR 72   // bf16 elems per B smem row; holds 64 k-elems, frag banks = 4g+tg (conflict-free)

__device__ __align__(16) float g_support[NROWS * NHID];
__device__ __align__(16) float g_z[NROWS * NHID];

// ---------------------------------------------------------------------------
__global__ void zero_scratch() {
    int i = blockIdx.x * blockDim.x + threadIdx.x;
    if (i < (NROWS * NHID) / 4) {
        ((float4*)g_support)[i] = make_float4(0.f, 0.f, 0.f, 0.f);
        ((float4*)g_z)[i]       = make_float4(0.f, 0.f, 0.f, 0.f);
    }
}

// fp32 pair -> packed bf16 hi pair + bf16 residual pair
__device__ __forceinline__ void split2(float x, float y, uint32_t& h, uint32_t& l) {
    __nv_bfloat162 hb = __floats2bfloat162_rn(x, y);
    float2 hf = __bfloat1622float2(hb);
    __nv_bfloat162 lb = __floats2bfloat162_rn(x - hf.x, y - hf.y);
    h = *reinterpret_cast<uint32_t*>(&hb);
    l = *reinterpret_cast<uint32_t*>(&lb);
}

#define MMA_BF16(dd, a, b0, b1)                                              \
    asm volatile(                                                            \
        "mma.sync.aligned.m16n8k16.row.col.f32.bf16.bf16.f32 "               \
        "{%0,%1,%2,%3}, {%4,%5,%6,%7}, {%8,%9}, {%0,%1,%2,%3};"              \
        : "+f"(dd[0]), "+f"(dd[1]), "+f"(dd[2]), "+f"(dd[3])                 \
        : "r"(a[0]), "r"(a[1]), "r"(a[2]), "r"(a[3]), "r"(b0), "r"(b1))

// ---------------------------------------------------------------------------
// C[M,32] += A[M,K] @ B[K,32], mma.sync bf16 split (hh+hl+lh).
// A fragments loaded DIRECTLY from global in mma layout (no smem round-trip).
// B (tiny) through double-buffered conflict-free smem. One barrier per chunk.
// ---------------------------------------------------------------------------
__global__ __launch_bounds__(256, 2)
void gemm_mma(const float* __restrict__ A, const float* __restrict__ B,
              float* __restrict__ C, int M, int K, int klen) {
    __shared__ __nv_bfloat16 Bh[2][32 * BSTR];
    __shared__ __nv_bfloat16 Bl[2][32 * BSTR];

    const int tid  = threadIdx.x;
    const int warp = tid >> 5, lane = tid & 31;
    const int g    = lane >> 2, tg = lane & 3;
    const int wm   = warp * 16;
    const int row0 = blockIdx.x * 128;
    const int kbeg = blockIdx.y * klen;          // even -> 8B-aligned float2
    const int kend = min(kbeg + klen, K);        // K even -> kend even
    const int nch  = (kend > kbeg) ? ((kend - kbeg + 63) >> 6) : 0;

    const int gr0 = row0 + wm + g;
    const bool r0ok = gr0 < M, r8ok = gr0 + 8 < M;
    const float* __restrict__ Ar0 = A + (size_t)gr0 * K;
    const float* __restrict__ Ar8 = Ar0 + (size_t)8 * K;

    float d[4][4];
#pragma unroll
    for (int i = 0; i < 4; i++)
#pragma unroll
        for (int j = 0; j < 4; j++) d[i][j] = 0.f;

    float2   va[16];            // raw A frags for one chunk
    float    vb[8];             // raw B slice
    uint32_t ah[4][4], al[4][4];
    const float2 f2z = make_float2(0.f, 0.f);

    // A frag loads: va[ks*4+{0,1,2,3}] = {r0 k, r8 k, r0 k+8, r8 k+8}
#define LOADA(k0)                                                              \
    {                                                                          \
        _Pragma("unroll")                                                      \
        for (int ks = 0; ks < 4; ks++) {                                       \
            int gk0 = (k0) + ks * 16 + tg * 2;                                 \
            int gk1 = gk0 + 8;                                                 \
            va[ks*4+0] = (r0ok && gk0 < kend) ? *(const float2*)(Ar0+gk0) : f2z; \
            va[ks*4+1] = (r8ok && gk0 < kend) ? *(const float2*)(Ar8+gk0) : f2z; \
            va[ks*4+2] = (r0ok && gk1 < kend) ? *(const float2*)(Ar0+gk1) : f2z; \
            va[ks*4+3] = (r8ok && gk1 < kend) ? *(const float2*)(Ar8+gk1) : f2z; \
        }                                                                      \
    }

#define LOADB(k0)                                                              \
    {                                                                          \
        _Pragma("unroll")                                                      \
        for (int i = 0; i < 2; i++) {                                          \
            int f = tid + i * 256;                                             \
            int n = f & 31, kq = f >> 5;   /* kq in [0,16) covers k 0..63 */   \
            _Pragma("unroll")                                                  \
            for (int j = 0; j < 4; j++) {                                      \
                int kk = (k0) + kq * 4 + j;                                    \
                vb[i*4+j] = (kk < kend) ? B[(size_t)kk * NHID + n] : 0.f;      \
            }                                                                  \
        }                                                                      \
    }

#define CONVA                                                                  \
    {                                                                          \
        _Pragma("unroll")                                                      \
        for (int ks = 0; ks < 4; ks++)                                         \
            _Pragma("unroll")                                                  \
            for (int j = 0; j < 4; j++)                                        \
                split2(va[ks*4+j].x, va[ks*4+j].y, ah[ks][j], al[ks][j]);      \
    }

#define STSB(bf)                                                               \
    {                                                                          \
        _Pragma("unroll")                                                      \
        for (int i = 0; i < 2; i++) {                                          \
            int f = tid + i * 256;                                             \
            int n = f & 31, kq = f >> 5;                                       \
            uint32_t h0, l0, h1, l1;                                           \
            split2(vb[i*4+0], vb[i*4+1], h0, l0);                              \
            split2(vb[i*4+2], vb[i*4+3], h1, l1);                              \
            int e = n * BSTR + kq * 4;    /* max 31*72+60+4 = 2296 < 2304 */   \
            *(uint2*)&Bh[bf][e] = make_uint2(h0, h1);                          \
            *(uint2*)&Bl[bf][e] = make_uint2(l0, l1);                          \
        }                                                                      \
    }

    if (nch > 0) {
        LOADA(kbeg); LOADB(kbeg);
        CONVA; STSB(0);
        __syncthreads();
    }

    for (int c = 0; c < nch; c++) {
        const int  buf  = c & 1;
        const bool more = (c + 1 < nch);
        const int  nk   = kbeg + (c + 1) * 64;

        if (more) { LOADA(nk); LOADB(nk); }   // latency hides behind MMAs

        // ---- compute chunk c ----
#pragma unroll
        for (int ks = 0; ks < 4; ks++) {
#pragma unroll
            for (int nt = 0; nt < 4; nt++) {
                int bb = (nt * 8 + g) * BSTR + ks * 16 + tg * 2;
                uint32_t bh0 = *(uint32_t*)&Bh[buf][bb];
                uint32_t bh1 = *(uint32_t*)&Bh[buf][bb + 8];
                uint32_t bl0 = *(uint32_t*)&Bl[buf][bb];
                uint32_t bl1 = *(uint32_t*)&Bl[buf][bb + 8];
                MMA_BF16(d[nt], ah[ks], bh0, bh1);   // hi*hi
                MMA_BF16(d[nt], ah[ks], bl0, bl1);   // hi*lo
                MMA_BF16(d[nt], al[ks], bh0, bh1);   // lo*hi
            }
        }

        if (more) { CONVA; STSB(buf ^ 1); }
        __syncthreads();
    }

    // ---- epilogue: split-K accumulate ----
#pragma unroll
    for (int nt = 0; nt < 4; nt++) {
        int c0 = nt * 8 + tg * 2;
        if (r0ok) {
            atomicAdd(&C[gr0 * NHID + c0],     d[nt][0]);
            atomicAdd(&C[gr0 * NHID + c0 + 1], d[nt][1]);
        }
        if (r8ok) {
            atomicAdd(&C[(gr0 + 8) * NHID + c0],     d[nt][2]);
            atomicAdd(&C[(gr0 + 8) * NHID + c0 + 1], d[nt][3]);
        }
    }
#undef LOADA
#undef LOADB
#undef CONVA
#undef STSB
}

// ---------------------------------------------------------------------------
__global__ __launch_bounds__(256)
void finalize_kernel(const float* __restrict__ b, const float* __restrict__ mu,
                     float* __restrict__ out) {
    int warp = (blockIdx.x * blockDim.x + threadIdx.x) >> 5;
    int h    = threadIdx.x & 31;
    if (warp >= NROWS) return;

    float z = g_z[warp * NHID + h] + b[h];
    out[warp * NHID + h] = z;

    float d2[KCLUS];
#pragma unroll
    for (int j = 0; j < KCLUS; j++) {
        float diff = z - mu[j * NHID + h];
        float v = diff * diff;
#pragma unroll
        for (int off = 16; off; off >>= 1)
            v += __shfl_xor_sync(0xffffffffu, v, off);
        d2[j] = v;
    }

    float qv[KCLUS];
    float ssum = 0.f;
#pragma unroll
    for (int j = 0; j < KCLUS; j++) {
        float base = 1.0f / (1.0f + d2[j] * 5.0f + 1e-8f);  // ALPHA = 0.2
        qv[j] = 0.5f * __powf(base, 1.2f);                  // ^(ALPHA+1) / 2
        ssum += qv[j];
    }
    if (h < KCLUS)
        out[NROWS * NHID + warp * KCLUS + h] = qv[h] / ssum;
}

// ---------------------------------------------------------------------------
extern "C" void kernel_launch(void* const* d_in, const int* in_sizes, int n_in,
                              void* d_out, int out_size) {
    const float* x   = (const float*)d_in[0];  // [10000, 3000]
    const float* adj = (const float*)d_in[1];  // [10000, 10000]
    const float* W   = (const float*)d_in[2];  // [3000, 32]
    const float* b   = (const float*)d_in[3];  // [32]
    const float* mu  = (const float*)d_in[4];  // [10, 32]
    float* out = (float*)d_out;                // z [10000,32] then q [10000,10]

    float *sup, *zbuf;
    cudaGetSymbolAddress((void**)&sup,  g_support);
    cudaGetSymbolAddress((void**)&zbuf, g_z);

    zero_scratch<<<(NROWS * NHID / 4 + 255) / 256, 256>>>();

    // support = x @ W : 79 row tiles x 2 K-splits
    {
        dim3 grid(79, 2);
        gemm_mma<<<grid, 256>>>(x, W, sup, NROWS, NFEAT, 1536);
    }
    // z = adj @ support : 79 row tiles x 4 K-splits
    {
        dim3 grid(79, 4);
        gemm_mma<<<grid, 256>>>(adj, sup, zbuf, NROWS, NROWS, 2560);
    }

    finalize_kernel<<<(NROWS * 32 + 255) / 256, 256>>>(b, mu, out);
}

// round 9
// speedup vs baseline: 4.8644x; 1.5043x over previous
#include <cuda_runtime.h>
#include <cuda_bf16.h>
#include <cstdint>

#define NROWS 10000
#define NFEAT 3000
#define NHID  32
#define KCLUS 10

#define BSTR 72                       // bf16 elems per B smem row (144 B stride)
#define BUFBYTES (32 * BSTR * 2)      // one B buffer: 4608 B

__device__ __align__(16) float g_support[NROWS * NHID];
__device__ __align__(16) float g_z[NROWS * NHID];

// ---------------------------------------------------------------------------
__global__ void zero_scratch() {
    int i = blockIdx.x * blockDim.x + threadIdx.x;
    if (i < (NROWS * NHID) / 4) {
        ((float4*)g_support)[i] = make_float4(0.f, 0.f, 0.f, 0.f);
        ((float4*)g_z)[i]       = make_float4(0.f, 0.f, 0.f, 0.f);
    }
}

__device__ __forceinline__ uint32_t s2u(const void* p) {
    uint32_t a;
    asm("{ .reg .u64 t; cvta.to.shared.u64 t, %1; cvt.u32.u64 %0, t; }" : "=r"(a) : "l"(p));
    return a;
}

// fp32 pair -> packed bf16 hi pair + bf16 residual pair
__device__ __forceinline__ void split2(float x, float y, uint32_t& h, uint32_t& l) {
    __nv_bfloat162 hb = __floats2bfloat162_rn(x, y);
    float2 hf = __bfloat1622float2(hb);
    __nv_bfloat162 lb = __floats2bfloat162_rn(x - hf.x, y - hf.y);
    h = *reinterpret_cast<uint32_t*>(&hb);
    l = *reinterpret_cast<uint32_t*>(&lb);
}

#define MMA_BF16(dd, a, b0, b1)                                              \
    asm volatile(                                                            \
        "mma.sync.aligned.m16n8k16.row.col.f32.bf16.bf16.f32 "               \
        "{%0,%1,%2,%3}, {%4,%5,%6,%7}, {%8,%9}, {%0,%1,%2,%3};"              \
        : "+f"(dd[0]), "+f"(dd[1]), "+f"(dd[2]), "+f"(dd[3])                 \
        : "r"(a[0]), "r"(a[1]), "r"(a[2]), "r"(a[3]), "r"(b0), "r"(b1))

#define LDSM4(r0, r1, r2, r3, addr)                                          \
    asm volatile(                                                            \
        "ldmatrix.sync.aligned.m8n8.x4.shared.b16 {%0,%1,%2,%3}, [%4];"      \
        : "=r"(r0), "=r"(r1), "=r"(r2), "=r"(r3) : "r"(addr))

// ---------------------------------------------------------------------------
// C[M,32] += A[M,K] @ B[K,32], mma.sync bf16 split (hh+hl+lh).
// A frags direct from global; B via double-buffered smem + ldmatrix.x4.
// MMAs grouped by product -> 4 independent accumulator chains.
// ---------------------------------------------------------------------------
__global__ __launch_bounds__(256, 2)
void gemm_mma(const float* __restrict__ A, const float* __restrict__ B,
              float* __restrict__ C, int M, int K, int klen) {
    __shared__ __nv_bfloat16 Bh[2][32 * BSTR];
    __shared__ __nv_bfloat16 Bl[2][32 * BSTR];

    const int tid  = threadIdx.x;
    const int warp = tid >> 5, lane = tid & 31;
    const int g    = lane >> 2, tg = lane & 3;
    const int wm   = warp * 16;
    const int row0 = blockIdx.x * 128;
    const int kbeg = blockIdx.y * klen;          // klen mult of 64 -> even
    const int kend = min(kbeg + klen, K);
    const int nch  = (kend > kbeg) ? ((kend - kbeg + 63) >> 6) : 0;

    const int gr0 = row0 + wm + g;
    const bool r0ok = gr0 < M, r8ok = gr0 + 8 < M;
    const float* __restrict__ Ar0 = A + (size_t)gr0 * K;
    const float* __restrict__ Ar8 = Ar0 + (size_t)8 * K;

    // ldmatrix per-lane addressing: tile lt = lane>>3 (n-half, k-half), row lr
    const int lt = lane >> 3, lr = lane & 7;
    const uint32_t bh0a = s2u(&Bh[0][0]);
    const uint32_t bl0a = s2u(&Bl[0][0]);
    // byte offset of this lane's row for n-pair p: n = p*16 + (lt>>1)*8 + lr
    uint32_t rowoff[2];
#pragma unroll
    for (int p = 0; p < 2; p++)
        rowoff[p] = (uint32_t)(((p * 16 + (lt >> 1) * 8 + lr) * BSTR) * 2 + (lt & 1) * 16);

    float d[4][4];
#pragma unroll
    for (int i = 0; i < 4; i++)
#pragma unroll
        for (int j = 0; j < 4; j++) d[i][j] = 0.f;

    float2   va[16];
    float    vb[8];
    uint32_t ah[4][4], al[4][4];
    const float2 f2z = make_float2(0.f, 0.f);

#define LOADA(k0)                                                              \
    {                                                                          \
        _Pragma("unroll")                                                      \
        for (int ks = 0; ks < 4; ks++) {                                       \
            int gk0 = (k0) + ks * 16 + tg * 2;                                 \
            int gk1 = gk0 + 8;                                                 \
            va[ks*4+0] = (r0ok && gk0 < kend) ? *(const float2*)(Ar0+gk0) : f2z; \
            va[ks*4+1] = (r8ok && gk0 < kend) ? *(const float2*)(Ar8+gk0) : f2z; \
            va[ks*4+2] = (r0ok && gk1 < kend) ? *(const float2*)(Ar0+gk1) : f2z; \
            va[ks*4+3] = (r8ok && gk1 < kend) ? *(const float2*)(Ar8+gk1) : f2z; \
        }                                                                      \
    }

#define LOADB(k0)                                                              \
    {                                                                          \
        _Pragma("unroll")                                                      \
        for (int i = 0; i < 2; i++) {                                          \
            int f = tid + i * 256;                                             \
            int n = f & 31, kq = f >> 5;                                       \
            _Pragma("unroll")                                                  \
            for (int j = 0; j < 4; j++) {                                      \
                int kk = (k0) + kq * 4 + j;                                    \
                vb[i*4+j] = (kk < kend) ? B[(size_t)kk * NHID + n] : 0.f;      \
            }                                                                  \
        }                                                                      \
    }

#define CONVA                                                                  \
    {                                                                          \
        _Pragma("unroll")                                                      \
        for (int ks = 0; ks < 4; ks++)                                         \
            _Pragma("unroll")                                                  \
            for (int j = 0; j < 4; j++)                                        \
                split2(va[ks*4+j].x, va[ks*4+j].y, ah[ks][j], al[ks][j]);      \
    }

#define STSB(bf)                                                               \
    {                                                                          \
        _Pragma("unroll")                                                      \
        for (int i = 0; i < 2; i++) {                                          \
            int f = tid + i * 256;                                             \
            int n = f & 31, kq = f >> 5;                                       \
            uint32_t h0, l0, h1, l1;                                           \
            split2(vb[i*4+0], vb[i*4+1], h0, l0);                              \
            split2(vb[i*4+2], vb[i*4+3], h1, l1);                              \
            int e = n * BSTR + kq * 4;                                         \
            *(uint2*)&Bh[bf][e] = make_uint2(h0, h1);                          \
            *(uint2*)&Bl[bf][e] = make_uint2(l0, l1);                          \
        }                                                                      \
    }

    if (nch > 0) {
        LOADA(kbeg); LOADB(kbeg);
        CONVA; STSB(0);
        __syncthreads();
    }

    for (int c = 0; c < nch; c++) {
        const int  buf  = c & 1;
        const bool more = (c + 1 < nch);
        const int  nk   = kbeg + (c + 1) * 64;
        const uint32_t bha = bh0a + buf * BUFBYTES;
        const uint32_t bla = bl0a + buf * BUFBYTES;

        if (more) { LOADA(nk); LOADB(nk); }   // LDG latency hides behind MMAs

        // ---- compute chunk c ----
#pragma unroll
        for (int ks = 0; ks < 4; ks++) {
            uint32_t bh[2][4], bl[2][4];
#pragma unroll
            for (int p = 0; p < 2; p++) {
                uint32_t ko = (uint32_t)(ks * 32);
                LDSM4(bh[p][0], bh[p][1], bh[p][2], bh[p][3], bha + rowoff[p] + ko);
                LDSM4(bl[p][0], bl[p][1], bl[p][2], bl[p][3], bla + rowoff[p] + ko);
            }
            // grouped by product: 4 independent accumulator chains each pass
#pragma unroll
            for (int j = 0; j < 4; j++)
                MMA_BF16(d[j], ah[ks], bh[j >> 1][(j & 1) * 2], bh[j >> 1][(j & 1) * 2 + 1]);
#pragma unroll
            for (int j = 0; j < 4; j++)
                MMA_BF16(d[j], ah[ks], bl[j >> 1][(j & 1) * 2], bl[j >> 1][(j & 1) * 2 + 1]);
#pragma unroll
            for (int j = 0; j < 4; j++)
                MMA_BF16(d[j], al[ks], bh[j >> 1][(j & 1) * 2], bh[j >> 1][(j & 1) * 2 + 1]);
        }

        if (more) { CONVA; STSB(buf ^ 1); }
        __syncthreads();
    }

    // ---- epilogue: split-K accumulate ----
#pragma unroll
    for (int nt = 0; nt < 4; nt++) {
        int c0 = nt * 8 + tg * 2;
        if (r0ok) {
            atomicAdd(&C[gr0 * NHID + c0],     d[nt][0]);
            atomicAdd(&C[gr0 * NHID + c0 + 1], d[nt][1]);
        }
        if (r8ok) {
            atomicAdd(&C[(gr0 + 8) * NHID + c0],     d[nt][2]);
            atomicAdd(&C[(gr0 + 8) * NHID + c0 + 1], d[nt][3]);
        }
    }
#undef LOADA
#undef LOADB
#undef CONVA
#undef STSB
}

// ---------------------------------------------------------------------------
__global__ __launch_bounds__(256)
void finalize_kernel(const float* __restrict__ b, const float* __restrict__ mu,
                     float* __restrict__ out) {
    int warp = (blockIdx.x * blockDim.x + threadIdx.x) >> 5;
    int h    = threadIdx.x & 31;
    if (warp >= NROWS) return;

    float z = g_z[warp * NHID + h] + b[h];
    out[warp * NHID + h] = z;

    float d2[KCLUS];
#pragma unroll
    for (int j = 0; j < KCLUS; j++) {
        float diff = z - mu[j * NHID + h];
        float v = diff * diff;
#pragma unroll
        for (int off = 16; off; off >>= 1)
            v += __shfl_xor_sync(0xffffffffu, v, off);
        d2[j] = v;
    }

    float qv[KCLUS];
    float ssum = 0.f;
#pragma unroll
    for (int j = 0; j < KCLUS; j++) {
        float base = 1.0f / (1.0f + d2[j] * 5.0f + 1e-8f);  // ALPHA = 0.2
        qv[j] = 0.5f * __powf(base, 1.2f);                  // ^(ALPHA+1) / 2
        ssum += qv[j];
    }
    if (h < KCLUS)
        out[NROWS * NHID + warp * KCLUS + h] = qv[h] / ssum;
}

// ---------------------------------------------------------------------------
extern "C" void kernel_launch(void* const* d_in, const int* in_sizes, int n_in,
                              void* d_out, int out_size) {
    const float* x   = (const float*)d_in[0];  // [10000, 3000]
    const float* adj = (const float*)d_in[1];  // [10000, 10000]
    const float* W   = (const float*)d_in[2];  // [3000, 32]
    const float* b   = (const float*)d_in[3];  // [32]
    const float* mu  = (const float*)d_in[4];  // [10, 32]
    float* out = (float*)d_out;                // z [10000,32] then q [10000,10]

    float *sup, *zbuf;
    cudaGetSymbolAddress((void**)&sup,  g_support);
    cudaGetSymbolAddress((void**)&zbuf, g_z);

    zero_scratch<<<(NROWS * NHID / 4 + 255) / 256, 256>>>();

    // support = x @ W : 79 tiles x 3 splits = 237 CTAs -> 1 wave x 16 chunks
    {
        dim3 grid(79, 3);
        gemm_mma<<<grid, 256>>>(x, W, sup, NROWS, NFEAT, 1024);
    }
    // z = adj @ support : 79 tiles x 7 splits = 553 CTAs -> 2 waves x 23 chunks
    {
        dim3 grid(79, 7);
        gemm_mma<<<grid, 256>>>(adj, sup, zbuf, NROWS, NROWS, 1472);
    }

    finalize_kernel<<<(NROWS * 32 + 255) / 256, 256>>>(b, mu, out);
}